// round 8
// baseline (speedup 1.0000x reference)
#include <cuda_runtime.h>
#include <cuda_fp16.h>

#define Bsz 4
#define S   2048
#define D   128
#define H   8
#define DK  16
#define BH  (Bsz*H)

typedef unsigned long long u64;
typedef unsigned int u32;

// 0.25 * log2(e): folded into Q at projection time so attention uses raw ex2
#define SCQ 0.36067376022224086f

// ---- scratch (no device allocations allowed) ----
__device__ float g_Q[BH*S*DK];                // pre-scaled by SCQ
__device__ float g_K[BH*S*DK];
__device__ float g_V[BH*S*DK];
__device__ __half g_E[(size_t)BH*S*S];        // 256 MB, [bh][m][q], per-column biased
__device__ float g_rcs[BH*S];                 // reciprocal of (biased) colsum
__device__ float g_maxqn[BH];                 // max ||Qhat|| per head (CS bound)
__device__ float g_head[Bsz*S*D];

// ---- packed fp32x2 helpers ----
__device__ __forceinline__ void ffma2(u64& d, u64 a, u64 b){
    asm("fma.rn.f32x2 %0, %1, %2, %0;" : "+l"(d) : "l"(a), "l"(b));
}
__device__ __forceinline__ u64 add2(u64 a, u64 b){
    u64 r; asm("add.rn.f32x2 %0, %1, %2;" : "=l"(r) : "l"(a), "l"(b)); return r;
}
__device__ __forceinline__ u64 pack2(float lo, float hi){
    u64 r; asm("mov.b64 %0, {%1, %2};" : "=l"(r) : "f"(lo), "f"(hi)); return r;
}
__device__ __forceinline__ u64 dup2(float x){
    u64 r; asm("mov.b64 %0, {%1, %1};" : "=l"(r) : "f"(x)); return r;
}
__device__ __forceinline__ float hsum2(u64 v){
    float lo, hi; asm("mov.b64 {%0, %1}, %2;" : "=f"(lo), "=f"(hi) : "l"(v));
    return lo + hi;
}
__device__ __forceinline__ float2 unpk(u64 v){
    float2 r; asm("mov.b64 {%0, %1}, %2;" : "=f"(r.x), "=f"(r.y) : "l"(v));
    return r;
}
__device__ __forceinline__ float ex2f(float x){
    float r; asm("ex2.approx.f32 %0, %1;" : "=f"(r) : "f"(x)); return r;
}
__device__ __forceinline__ u64 lds64(const float* p){
    return *reinterpret_cast<const u64*>(p);
}
__device__ __forceinline__ u64 ldg64(const float* p){
    return *reinterpret_cast<const u64*>(p);
}

// ============================================================
// Kernel 1: Q/K/V projections. grid (B*S/64, 3), 128 threads.
// ============================================================
__global__ void proj_kernel(const float* __restrict__ x,
                            const float* __restrict__ wq,
                            const float* __restrict__ wk,
                            const float* __restrict__ wv) {
    __shared__ float xs[64][132];
    __shared__ float wsT[16][132];
    const int t = threadIdx.x;       // 128
    const int row0 = blockIdx.x * 64;
    const int pj = blockIdx.y;
    const float* W0 = (pj == 0 ? wq : pj == 1 ? wk : wv);
    float* dst = (pj == 0 ? g_Q : pj == 1 ? g_K : g_V);
    const float oscale = (pj == 0) ? SCQ : 1.0f;

    #pragma unroll
    for (int k = 0; k < 16; k++) {
        int idx = t + k*128;
        int r = idx >> 5, q4 = idx & 31;
        *reinterpret_cast<float4*>(&xs[r][q4*4]) =
            *reinterpret_cast<const float4*>(x + (row0 + r)*D + q4*4);
    }

    const int rg = t >> 3, cg = t & 7;
    for (int h = 0; h < H; h++) {
        __syncthreads();
        #pragma unroll
        for (int k = 0; k < 4; k++) {
            int idx = t + k*128;
            int d = idx >> 2, c4 = idx & 3;
            float4 v = *reinterpret_cast<const float4*>(W0 + h*D*DK + d*DK + c4*4);
            wsT[c4*4+0][d] = v.x; wsT[c4*4+1][d] = v.y;
            wsT[c4*4+2][d] = v.z; wsT[c4*4+3][d] = v.w;
        }
        __syncthreads();

        u64 acc[4][2] = {};
        #pragma unroll 8
        for (int d = 0; d < D; d += 2) {
            u64 w0 = lds64(&wsT[cg][d]);
            u64 w1 = lds64(&wsT[cg+8][d]);
            #pragma unroll
            for (int i = 0; i < 4; i++) {
                u64 xv = lds64(&xs[rg*4+i][d]);
                ffma2(acc[i][0], xv, w0);
                ffma2(acc[i][1], xv, w1);
            }
        }
        #pragma unroll
        for (int i = 0; i < 4; i++) {
            int grow = row0 + rg*4 + i;
            int b = grow >> 11, s = grow & (S-1);
            float* o = dst + ((b*H + h)*S + s)*DK;
            o[cg]   = hsum2(acc[i][0]) * oscale;
            o[cg+8] = hsum2(acc[i][1]) * oscale;
        }
    }
}

// ============================================================
// Kernel 1b: maxQnorm[bh] = max_q ||Qhat[q]||. grid BH, 256 threads.
// Deterministic tree reduction (max is order-independent anyway).
// ============================================================
__global__ void __launch_bounds__(256) qnorm_kernel() {
    __shared__ float red[256];
    const int bh = blockIdx.x, t = threadIdx.x;
    const float* Qb = g_Q + bh*S*DK;
    float mx = 0.f;
    for (int r = t; r < S; r += 256) {
        u64 a = 0;
        #pragma unroll
        for (int j = 0; j < 8; j++) {
            u64 q = ldg64(Qb + r*DK + 2*j);
            ffma2(a, q, q);
        }
        mx = fmaxf(mx, hsum2(a));
    }
    red[t] = mx;
    __syncthreads();
    #pragma unroll
    for (int s2 = 128; s2; s2 >>= 1) {
        if (t < s2) red[t] = fmaxf(red[t], red[t + s2]);
        __syncthreads();
    }
    if (t == 0) g_maxqn[bh] = sqrtf(red[0]);
}

// ============================================================
// Kernel 2: E[m][q] = 2^(Qhat[q].K[m] - b_m) as fp16 with
// b_m = maxQnorm*||K[m]|| - 8  (Cauchy-Schwarz: stored E <= 2^8,
// overflow IMPOSSIBLE; bias cancels exactly in E/colsum).
// grid (S/128, BH), 128 threads. Thread owns m-column: K[m] + colsum
// in regs, Q broadcast from SMEM. No shuffles.
// ============================================================
__global__ void __launch_bounds__(128) scoresE_kernel() {
    __shared__ float Qs[128][16];
    const int t  = threadIdx.x;
    const int bh = blockIdx.y;
    const int m  = blockIdx.x*128 + t;
    const float* Kb = g_K + (bh*S + m)*DK;
    const float* Qb = g_Q + bh*S*DK;
    __half* Em = g_E + (size_t)bh*S*S + (size_t)m*S;

    u64 k[8];
    #pragma unroll
    for (int j = 0; j < 8; j++) k[j] = ldg64(Kb + 2*j);

    // Cauchy-Schwarz column bias: arg <= ||Qhat||max * ||K[m]||
    float bm;
    {
        u64 a = 0;
        #pragma unroll
        for (int j = 0; j < 8; j++) ffma2(a, k[j], k[j]);
        bm = sqrtf(hsum2(a)) * g_maxqn[bh] - 8.0f;
    }
    const u64 bias = pack2(-bm, 0.0f);
    float cs = 0.f;

    for (int q0 = 0; q0 < S; q0 += 128) {
        __syncthreads();
        #pragma unroll
        for (int i = 0; i < 4; i++) {
            int idx = t + i*128;
            int r = idx >> 2, c4 = idx & 3;
            *reinterpret_cast<float4*>(&Qs[r][c4*4]) =
                *reinterpret_cast<const float4*>(Qb + (q0 + r)*DK + c4*4);
        }
        __syncthreads();

        for (int q8 = 0; q8 < 16; q8++) {
            u32 ebuf[4];
            #pragma unroll
            for (int qp2 = 0; qp2 < 4; qp2++) {
                float e[2];
                #pragma unroll
                for (int u = 0; u < 2; u++) {
                    const int qq = q8*8 + qp2*2 + u;
                    const ulonglong2* qp = reinterpret_cast<const ulonglong2*>(&Qs[qq][0]);
                    u64 a0 = bias, a1 = 0;
                    ulonglong2 v0 = qp[0], v1 = qp[1];   // LDS.128 broadcast
                    ffma2(a0, v0.x, k[0]); ffma2(a1, v0.y, k[1]);
                    ffma2(a0, v1.x, k[2]); ffma2(a1, v1.y, k[3]);
                    ulonglong2 v2 = qp[2], v3 = qp[3];
                    ffma2(a0, v2.x, k[4]); ffma2(a1, v2.y, k[5]);
                    ffma2(a0, v3.x, k[6]); ffma2(a1, v3.y, k[7]);
                    // bound guarantees <= 2^8; fmin is dead insurance only
                    e[u] = fminf(ex2f(hsum2(add2(a0, a1))), 65472.0f);
                    cs += e[u];
                }
                __half2 h2 = __floats2half2_rn(e[0], e[1]);
                ebuf[qp2] = *reinterpret_cast<u32*>(&h2);
            }
            *reinterpret_cast<uint4*>(Em + q0 + q8*8) =
                make_uint4(ebuf[0], ebuf[1], ebuf[2], ebuf[3]);
        }
    }
    g_rcs[bh*S + m] = __frcp_rn(cs);       // b_m cancels in E/cs
}

// ============================================================
// Kernel 3: out[q,:] = sum_m E[m][q] * (V[m,:]*rcs[m]).
// grid (S/128, BH), 128 threads. Lane owns 4 q rows (ILP);
// warps split m 4 ways; V' broadcast from SMEM via LDS.128.
// ============================================================
__global__ void __launch_bounds__(128) ev_kernel() {
    __shared__ float Vs[128][16];
    __shared__ float red[3][128][17];
    const int t    = threadIdx.x;
    const int w    = t >> 5, lane = t & 31;
    const int bh   = blockIdx.y;
    const int q0   = blockIdx.x * 128;
    const float* Vb  = g_V + bh*S*DK;
    const float* rcs = g_rcs + bh*S;
    const __half* Eb = g_E + (size_t)bh*S*S;

    u64 acc[4][8] = {};                    // 4 q-rows x 8 v-pairs

    for (int m0 = 0; m0 < S; m0 += 128) {
        __syncthreads();
        #pragma unroll
        for (int i = 0; i < 4; i++) {
            int idx = t + i*128;
            int r = idx >> 2, c4 = idx & 3;
            float4 v = *reinterpret_cast<const float4*>(Vb + (m0 + r)*DK + c4*4);
            float rc = rcs[m0 + r];
            v.x *= rc; v.y *= rc; v.z *= rc; v.w *= rc;
            *reinterpret_cast<float4*>(&Vs[r][c4*4]) = v;
        }
        __syncthreads();

        const int mbase = w * 32;
        #pragma unroll 4
        for (int mi = 0; mi < 32; mi++) {
            const int m  = mbase + mi;
            const int mg = m0 + m;
            uint2 eu = *reinterpret_cast<const uint2*>(
                Eb + (size_t)mg*S + q0 + 4*lane);          // coalesced 256B/warp
            float2 e01 = __half22float2(*reinterpret_cast<__half2*>(&eu.x));
            float2 e23 = __half22float2(*reinterpret_cast<__half2*>(&eu.y));
            u64 E0 = dup2(e01.x), E1 = dup2(e01.y);
            u64 E2 = dup2(e23.x), E3 = dup2(e23.y);
            const ulonglong2* vp = reinterpret_cast<const ulonglong2*>(&Vs[m][0]);
            #pragma unroll
            for (int p = 0; p < 4; p++) {
                ulonglong2 vv = vp[p];                     // LDS.128 broadcast
                ffma2(acc[0][2*p], E0, vv.x); ffma2(acc[0][2*p+1], E0, vv.y);
                ffma2(acc[1][2*p], E1, vv.x); ffma2(acc[1][2*p+1], E1, vv.y);
                ffma2(acc[2][2*p], E2, vv.x); ffma2(acc[2][2*p+1], E2, vv.y);
                ffma2(acc[3][2*p], E3, vv.x); ffma2(acc[3][2*p+1], E3, vv.y);
            }
        }
    }

    // cross-warp reduction over the 4 m-slices
    __syncthreads();
    if (w) {
        #pragma unroll
        for (int qi = 0; qi < 4; qi++)
            #pragma unroll
            for (int j = 0; j < 8; j++) {
                float2 p = unpk(acc[qi][j]);
                red[w-1][4*lane+qi][2*j]   = p.x;
                red[w-1][4*lane+qi][2*j+1] = p.y;
            }
    }
    __syncthreads();
    if (w == 0) {
        const int b = bh >> 3, h = bh & 7;
        #pragma unroll
        for (int qi = 0; qi < 4; qi++) {
            float o[16];
            #pragma unroll
            for (int j = 0; j < 8; j++) {
                float2 p = unpk(acc[qi][j]);
                o[2*j] = p.x; o[2*j+1] = p.y;
            }
            #pragma unroll
            for (int sl = 0; sl < 3; sl++)
                #pragma unroll
                for (int c = 0; c < 16; c++)
                    o[c] += red[sl][4*lane+qi][c];
            float* d0 = g_head + (b*S + q0 + 4*lane + qi)*D + h*DK;
            #pragma unroll
            for (int c4 = 0; c4 < 4; c4++)
                *reinterpret_cast<float4*>(d0 + c4*4) =
                    make_float4(o[c4*4], o[c4*4+1], o[c4*4+2], o[c4*4+3]);
        }
    }
}

// ============================================================
// Kernel 4: out = head[B*S,128] @ w_o[128,128]. grid 256, 256 thr.
// ============================================================
__global__ void final_proj_kernel(const float* __restrict__ wo,
                                  float* __restrict__ out) {
    __shared__ float hsT[128][34];
    const int t = threadIdx.x;
    const int row0 = blockIdx.x * 32;

    #pragma unroll
    for (int k = 0; k < 4; k++) {
        int idx = t + k*256;
        int r = idx >> 5, j4 = idx & 31;
        float4 v = *reinterpret_cast<const float4*>(g_head + (row0 + r)*D + j4*4);
        hsT[j4*4+0][r] = v.x; hsT[j4*4+1][r] = v.y;
        hsT[j4*4+2][r] = v.z; hsT[j4*4+3][r] = v.w;
    }
    __syncthreads();

    const int c = t & 127, rh = t >> 7;
    u64 acc[8] = {};
    #pragma unroll 4
    for (int j = 0; j < D; j++) {
        u64 w = dup2(wo[j*D + c]);
        #pragma unroll
        for (int p = 0; p < 8; p++)
            ffma2(acc[p], lds64(&hsT[j][rh*16 + 2*p]), w);
    }
    #pragma unroll
    for (int p = 0; p < 8; p++) {
        float2 v = unpk(acc[p]);
        int r = row0 + rh*16 + 2*p;
        out[r*D + c]     = v.x;
        out[(r+1)*D + c] = v.y;
    }
}

// ============================================================
extern "C" void kernel_launch(void* const* d_in, const int* in_sizes, int n_in,
                              void* d_out, int out_size) {
    const float* x  = (const float*)d_in[0];
    const float* wq = (const float*)d_in[1];
    const float* wk = (const float*)d_in[2];
    const float* wv = (const float*)d_in[3];
    const float* wo = (const float*)d_in[4];
    float* out = (float*)d_out;

    proj_kernel      <<< dim3(Bsz*S/64, 3), 128 >>>(x, wq, wk, wv);
    qnorm_kernel     <<< BH,                256 >>>();
    scoresE_kernel   <<< dim3(S/128, BH),   128 >>>();
    ev_kernel        <<< dim3(S/128, BH),   128 >>>();
    final_proj_kernel<<< Bsz*S/32,          256 >>>(wo, out);
}

// round 9
// speedup vs baseline: 1.0875x; 1.0875x over previous
#include <cuda_runtime.h>
#include <cuda_fp16.h>

#define Bsz 4
#define S   2048
#define D   128
#define H   8
#define DK  16
#define BH  (Bsz*H)

typedef unsigned long long u64;
typedef unsigned int u32;

// 0.25 * log2(e): folded into Q at projection time so attention uses raw ex2
#define SCQ 0.36067376022224086f

// ---- scratch (no device allocations allowed) ----
__device__ float g_Q[BH*S*DK];                // pre-scaled by SCQ
__device__ float g_K[BH*S*DK];
__device__ float g_V[BH*S*DK];
__device__ __half g_E[(size_t)BH*S*S];        // 256 MB, [bh][m][q], per-column biased
__device__ float g_rcs[BH*S];                 // reciprocal of (biased) colsum
__device__ float g_maxqn[BH];                 // max ||Qhat|| per head (CS bound)
__device__ float g_head[Bsz*S*D];

// ---- packed fp32x2 helpers ----
__device__ __forceinline__ void ffma2(u64& d, u64 a, u64 b){
    asm("fma.rn.f32x2 %0, %1, %2, %0;" : "+l"(d) : "l"(a), "l"(b));
}
__device__ __forceinline__ u64 add2(u64 a, u64 b){
    u64 r; asm("add.rn.f32x2 %0, %1, %2;" : "=l"(r) : "l"(a), "l"(b)); return r;
}
__device__ __forceinline__ u64 pack2(float lo, float hi){
    u64 r; asm("mov.b64 %0, {%1, %2};" : "=l"(r) : "f"(lo), "f"(hi)); return r;
}
__device__ __forceinline__ u64 dup2(float x){
    u64 r; asm("mov.b64 %0, {%1, %1};" : "=l"(r) : "f"(x)); return r;
}
__device__ __forceinline__ float hsum2(u64 v){
    float lo, hi; asm("mov.b64 {%0, %1}, %2;" : "=f"(lo), "=f"(hi) : "l"(v));
    return lo + hi;
}
__device__ __forceinline__ float2 unpk(u64 v){
    float2 r; asm("mov.b64 {%0, %1}, %2;" : "=f"(r.x), "=f"(r.y) : "l"(v));
    return r;
}
__device__ __forceinline__ float ex2f(float x){
    float r; asm("ex2.approx.f32 %0, %1;" : "=f"(r) : "f"(x)); return r;
}
__device__ __forceinline__ u64 lds64(const float* p){
    return *reinterpret_cast<const u64*>(p);
}
__device__ __forceinline__ u64 ldg64(const float* p){
    return *reinterpret_cast<const u64*>(p);
}

// ============================================================
// Kernel 1: Q/K/V projections. grid (B*S/64, 3), 128 threads.
// ============================================================
__global__ void proj_kernel(const float* __restrict__ x,
                            const float* __restrict__ wq,
                            const float* __restrict__ wk,
                            const float* __restrict__ wv) {
    __shared__ float xs[64][132];
    __shared__ float wsT[16][132];
    const int t = threadIdx.x;       // 128
    const int row0 = blockIdx.x * 64;
    const int pj = blockIdx.y;
    const float* W0 = (pj == 0 ? wq : pj == 1 ? wk : wv);
    float* dst = (pj == 0 ? g_Q : pj == 1 ? g_K : g_V);
    const float oscale = (pj == 0) ? SCQ : 1.0f;

    #pragma unroll
    for (int k = 0; k < 16; k++) {
        int idx = t + k*128;
        int r = idx >> 5, q4 = idx & 31;
        *reinterpret_cast<float4*>(&xs[r][q4*4]) =
            *reinterpret_cast<const float4*>(x + (row0 + r)*D + q4*4);
    }

    const int rg = t >> 3, cg = t & 7;
    for (int h = 0; h < H; h++) {
        __syncthreads();
        #pragma unroll
        for (int k = 0; k < 4; k++) {
            int idx = t + k*128;
            int d = idx >> 2, c4 = idx & 3;
            float4 v = *reinterpret_cast<const float4*>(W0 + h*D*DK + d*DK + c4*4);
            wsT[c4*4+0][d] = v.x; wsT[c4*4+1][d] = v.y;
            wsT[c4*4+2][d] = v.z; wsT[c4*4+3][d] = v.w;
        }
        __syncthreads();

        u64 acc[4][2] = {};
        #pragma unroll 8
        for (int d = 0; d < D; d += 2) {
            u64 w0 = lds64(&wsT[cg][d]);
            u64 w1 = lds64(&wsT[cg+8][d]);
            #pragma unroll
            for (int i = 0; i < 4; i++) {
                u64 xv = lds64(&xs[rg*4+i][d]);
                ffma2(acc[i][0], xv, w0);
                ffma2(acc[i][1], xv, w1);
            }
        }
        #pragma unroll
        for (int i = 0; i < 4; i++) {
            int grow = row0 + rg*4 + i;
            int b = grow >> 11, s = grow & (S-1);
            float* o = dst + ((b*H + h)*S + s)*DK;
            o[cg]   = hsum2(acc[i][0]) * oscale;
            o[cg+8] = hsum2(acc[i][1]) * oscale;
        }
    }
}

// ============================================================
// Kernel 1b: maxQnorm[bh] = max_q ||Qhat[q]||. grid BH, 256 threads.
// ============================================================
__global__ void __launch_bounds__(256) qnorm_kernel() {
    __shared__ float red[256];
    const int bh = blockIdx.x, t = threadIdx.x;
    const float* Qb = g_Q + bh*S*DK;
    float mx = 0.f;
    for (int r = t; r < S; r += 256) {
        u64 a = 0;
        #pragma unroll
        for (int j = 0; j < 8; j++) {
            u64 q = ldg64(Qb + r*DK + 2*j);
            ffma2(a, q, q);
        }
        mx = fmaxf(mx, hsum2(a));
    }
    red[t] = mx;
    __syncthreads();
    #pragma unroll
    for (int s2 = 128; s2; s2 >>= 1) {
        if (t < s2) red[t] = fmaxf(red[t], red[t + s2]);
        __syncthreads();
    }
    if (t == 0) g_maxqn[bh] = sqrtf(red[0]);
}

// ============================================================
// Kernel 2: E[m][q] = 2^(Qhat[q].K[m] - b_m) fp16, COALESCED stores
// (lane = q pair -> contiguous 128B/warp). b_m = maxQn*||K[m]|| - 8
// (Cauchy-Schwarz: E <= 2^8, overflow impossible), computed per
// staged K-chunk in SMEM. No shuffles, no colsum here.
// grid (S/64, BH), 128 threads (4 warps split each 128-m chunk).
// ============================================================
__global__ void __launch_bounds__(128) scoresE_kernel() {
    __shared__ float Ks[128][16];
    __shared__ float bs[128];
    const int t = threadIdx.x, w = t >> 5, lane = t & 31;
    const int bh = blockIdx.y;
    const int q0 = blockIdx.x * 64;
    const float* Qb = g_Q + bh*S*DK;
    const float* Kb = g_K + bh*S*DK;
    __half* Eb = g_E + (size_t)bh*S*S;
    const float mq = g_maxqn[bh];

    u64 qa[8], qb[8];
    #pragma unroll
    for (int j = 0; j < 8; j++) {
        qa[j] = ldg64(Qb + (q0 + 2*lane)*DK + 2*j);
        qb[j] = ldg64(Qb + (q0 + 2*lane + 1)*DK + 2*j);
    }

    for (int m0 = 0; m0 < S; m0 += 128) {
        __syncthreads();                       // Ks/bs reuse
        #pragma unroll
        for (int i = 0; i < 4; i++) {
            int idx = t + i*128;
            int r = idx >> 2, c4 = idx & 3;
            *reinterpret_cast<float4*>(&Ks[r][c4*4]) =
                *reinterpret_cast<const float4*>(Kb + (m0 + r)*DK + c4*4);
        }
        __syncthreads();
        {   // per-row CS bias from SMEM (1 row per thread)
            const ulonglong2* kp = reinterpret_cast<const ulonglong2*>(&Ks[t][0]);
            u64 a = 0;
            #pragma unroll
            for (int p = 0; p < 4; p++) {
                ulonglong2 kv = kp[p];
                ffma2(a, kv.x, kv.x);
                ffma2(a, kv.y, kv.y);
            }
            bs[t] = fmaf(sqrtf(hsum2(a)), mq, -8.0f);
        }
        __syncthreads();

        const int mbase = w * 32;
        #pragma unroll 4
        for (int mi = 0; mi < 32; mi++) {
            const int m  = mbase + mi;
            const int mg = m0 + m;
            const u64 bias = pack2(-bs[m], 0.0f);    // broadcast LDS
            const ulonglong2* kp = reinterpret_cast<const ulonglong2*>(&Ks[m][0]);
            u64 a0 = bias, a1 = 0, a2 = bias, a3 = 0;
            #pragma unroll
            for (int p = 0; p < 4; p++) {
                ulonglong2 kv = kp[p];               // LDS.128 broadcast
                ffma2(a0, qa[2*p],   kv.x);
                ffma2(a1, qa[2*p+1], kv.y);
                ffma2(a2, qb[2*p],   kv.x);
                ffma2(a3, qb[2*p+1], kv.y);
            }
            // bound guarantees <= 2^8; fmin is dead insurance only
            float e0 = fminf(ex2f(hsum2(add2(a0, a1))), 65472.0f);
            float e1 = fminf(ex2f(hsum2(add2(a2, a3))), 65472.0f);
            // coalesced 128B/warp fp16x2 store
            *reinterpret_cast<__half2*>(Eb + (size_t)mg*S + q0 + 2*lane) =
                __floats2half2_rn(e0, e1);
        }
    }
}

// ============================================================
// Kernel 2b: rcs[m] = 1 / sum_q E[m][q] from the STORED fp16 values
// (exactly consistent with what ev consumes). One warp per m-row,
// coalesced uint4 loads. grid BH*S/8, 256 threads.
// ============================================================
__global__ void __launch_bounds__(256) colsumE_kernel() {
    const int w = threadIdx.x >> 5, lane = threadIdx.x & 31;
    const size_t row = (size_t)blockIdx.x*8 + w;       // [0, BH*S)
    const __half* Er = g_E + row*S;
    float s = 0.f;
    #pragma unroll
    for (int i = 0; i < 8; i++) {
        uint4 u = *reinterpret_cast<const uint4*>(Er + i*256 + lane*8);
        float2 f0 = __half22float2(*reinterpret_cast<__half2*>(&u.x));
        float2 f1 = __half22float2(*reinterpret_cast<__half2*>(&u.y));
        float2 f2 = __half22float2(*reinterpret_cast<__half2*>(&u.z));
        float2 f3 = __half22float2(*reinterpret_cast<__half2*>(&u.w));
        s += (f0.x + f0.y) + (f1.x + f1.y) + (f2.x + f2.y) + (f3.x + f3.y);
    }
    #pragma unroll
    for (int off = 16; off; off >>= 1)
        s += __shfl_xor_sync(0xffffffffu, s, off);
    if (lane == 0) g_rcs[row] = __frcp_rn(s);
}

// ============================================================
// Kernel 3: out[q,:] = sum_m E[m][q] * (V[m,:]*rcs[m]).
// grid (S/64, BH), 128 threads. Lane owns q rows {2l, 2l+1};
// warps split m 4 ways; V' broadcast from SMEM via LDS.128.
// (R5 shape: measured 145us, occ ~41%.)
// ============================================================
__global__ void __launch_bounds__(128) ev_kernel() {
    __shared__ float Vs[128][16];
    __shared__ float red[3][64][18];
    const int t    = threadIdx.x;
    const int w    = t >> 5, lane = t & 31;
    const int bh   = blockIdx.y;
    const int q0   = blockIdx.x * 64;
    const float* Vb  = g_V + bh*S*DK;
    const float* rcs = g_rcs + bh*S;
    const __half* Eb = g_E + (size_t)bh*S*S;

    u64 acc0[8] = {}, acc1[8] = {};

    for (int m0 = 0; m0 < S; m0 += 128) {
        __syncthreads();
        #pragma unroll
        for (int i = 0; i < 4; i++) {
            int idx = t + i*128;
            int r = idx >> 2, c4 = idx & 3;
            float4 v = *reinterpret_cast<const float4*>(Vb + (m0 + r)*DK + c4*4);
            float rc = rcs[m0 + r];
            v.x *= rc; v.y *= rc; v.z *= rc; v.w *= rc;
            *reinterpret_cast<float4*>(&Vs[r][c4*4]) = v;
        }
        __syncthreads();

        const int mbase = w * 32;
        #pragma unroll 4
        for (int mi = 0; mi < 32; mi++) {
            const int m  = mbase + mi;
            const int mg = m0 + m;
            __half2 eh = *reinterpret_cast<const __half2*>(
                Eb + (size_t)mg*S + q0 + 2*lane);          // coalesced 128B/warp
            float2 ef = __half22float2(eh);
            u64 E0 = dup2(ef.x), E1 = dup2(ef.y);
            const ulonglong2* vp = reinterpret_cast<const ulonglong2*>(&Vs[m][0]);
            #pragma unroll
            for (int p = 0; p < 4; p++) {
                ulonglong2 vv = vp[p];                     // LDS.128 broadcast
                ffma2(acc0[2*p],   E0, vv.x);
                ffma2(acc0[2*p+1], E0, vv.y);
                ffma2(acc1[2*p],   E1, vv.x);
                ffma2(acc1[2*p+1], E1, vv.y);
            }
        }
    }

    // cross-warp reduction over the 4 m-slices
    __syncthreads();
    if (w) {
        #pragma unroll
        for (int j = 0; j < 8; j++) {
            float2 p0 = unpk(acc0[j]), p1 = unpk(acc1[j]);
            red[w-1][2*lane][2*j]       = p0.x;
            red[w-1][2*lane][2*j+1]     = p0.y;
            red[w-1][2*lane+1][2*j]     = p1.x;
            red[w-1][2*lane+1][2*j+1]   = p1.y;
        }
    }
    __syncthreads();
    if (w == 0) {
        const int b = bh >> 3, h = bh & 7;
        float o0[16], o1[16];
        #pragma unroll
        for (int j = 0; j < 8; j++) {
            float2 p0 = unpk(acc0[j]), p1 = unpk(acc1[j]);
            o0[2*j] = p0.x; o0[2*j+1] = p0.y;
            o1[2*j] = p1.x; o1[2*j+1] = p1.y;
        }
        #pragma unroll
        for (int sl = 0; sl < 3; sl++)
            #pragma unroll
            for (int c = 0; c < 16; c++) {
                o0[c] += red[sl][2*lane][c];
                o1[c] += red[sl][2*lane+1][c];
            }
        float* d0 = g_head + (b*S + q0 + 2*lane)*D     + h*DK;
        float* d1 = g_head + (b*S + q0 + 2*lane + 1)*D + h*DK;
        #pragma unroll
        for (int c4 = 0; c4 < 4; c4++) {
            *reinterpret_cast<float4*>(d0 + c4*4) =
                make_float4(o0[c4*4], o0[c4*4+1], o0[c4*4+2], o0[c4*4+3]);
            *reinterpret_cast<float4*>(d1 + c4*4) =
                make_float4(o1[c4*4], o1[c4*4+1], o1[c4*4+2], o1[c4*4+3]);
        }
    }
}

// ============================================================
// Kernel 4: out = head[B*S,128] @ w_o[128,128]. grid 256, 256 thr.
// ============================================================
__global__ void final_proj_kernel(const float* __restrict__ wo,
                                  float* __restrict__ out) {
    __shared__ float hsT[128][34];
    const int t = threadIdx.x;
    const int row0 = blockIdx.x * 32;

    #pragma unroll
    for (int k = 0; k < 4; k++) {
        int idx = t + k*256;
        int r = idx >> 5, j4 = idx & 31;
        float4 v = *reinterpret_cast<const float4*>(g_head + (row0 + r)*D + j4*4);
        hsT[j4*4+0][r] = v.x; hsT[j4*4+1][r] = v.y;
        hsT[j4*4+2][r] = v.z; hsT[j4*4+3][r] = v.w;
    }
    __syncthreads();

    const int c = t & 127, rh = t >> 7;
    u64 acc[8] = {};
    #pragma unroll 4
    for (int j = 0; j < D; j++) {
        u64 w = dup2(wo[j*D + c]);
        #pragma unroll
        for (int p = 0; p < 8; p++)
            ffma2(acc[p], lds64(&hsT[j][rh*16 + 2*p]), w);
    }
    #pragma unroll
    for (int p = 0; p < 8; p++) {
        float2 v = unpk(acc[p]);
        int r = row0 + rh*16 + 2*p;
        out[r*D + c]     = v.x;
        out[(r+1)*D + c] = v.y;
    }
}

// ============================================================
extern "C" void kernel_launch(void* const* d_in, const int* in_sizes, int n_in,
                              void* d_out, int out_size) {
    const float* x  = (const float*)d_in[0];
    const float* wq = (const float*)d_in[1];
    const float* wk = (const float*)d_in[2];
    const float* wv = (const float*)d_in[3];
    const float* wo = (const float*)d_in[4];
    float* out = (float*)d_out;

    proj_kernel      <<< dim3(Bsz*S/64, 3), 128 >>>(x, wq, wk, wv);
    qnorm_kernel     <<< BH,                256 >>>();
    scoresE_kernel   <<< dim3(S/64, BH),    128 >>>();
    colsumE_kernel   <<< BH*S/8,            256 >>>();
    ev_kernel        <<< dim3(S/64, BH),    128 >>>();
    final_proj_kernel<<< Bsz*S/32,          256 >>>(wo, out);
}